// round 8
// baseline (speedup 1.0000x reference)
#include <cuda_runtime.h>

#define NEGINF __int_as_float(0xff800000)

// Problem constants
#define B_ 8
#define C_ 64
#define H_ 64
#define W_ 64
#define O_ 64
#define CC 8    // channel chunk held in smem

// Block: 128 threads.
//   wq     = tid & 31      (0..31) -> output cols wq*2, wq*2+1
//   h_pair = (tid >> 5)&1  (0..1)  -> output rows h0 + h_pair*2 + {0,1}
//   og     = tid >> 6      (0..1)  -> o_local = og*4 .. og*4+3
// Block covers: one b, h-tile of 4 rows, full W=64, o-tile of 8 (2048 outputs).
// Grid: (16 h-tiles, 8 o-tiles, 8 batch) = 1024 blocks (6.9/SM, balanced wave).
// Per thread: 4 o x 2 w x 2 h = 16 outputs.

__device__ __forceinline__ unsigned long long addx2(unsigned long long a, unsigned long long b) {
    unsigned long long r;
    asm("add.rn.f32x2 %0, %1, %2;" : "=l"(r) : "l"(a), "l"(b));
    return r;
}
__device__ __forceinline__ unsigned long long pack2(float lo, float hi) {
    unsigned long long r;
    asm("mov.b64 %0, {%1, %2};" : "=l"(r) : "f"(lo), "f"(hi));
    return r;
}
__device__ __forceinline__ void unpack2(unsigned long long v, float& lo, float& hi) {
    asm("mov.b64 {%0, %1}, %2;" : "=f"(lo), "=f"(hi) : "l"(v));
}

__global__ __launch_bounds__(128, 7) void maxplus_conv_kernel(
    const float* __restrict__ x,
    const float* __restrict__ kern,
    float* __restrict__ out)
{
    // x tile: rows h0-1 .. h0+4 (6 rows), cols -1..64 (tile cols 0..65), stride 66 (8B-aligned rows)
    __shared__ __align__(16) float xs[CC][6][66];
    // kernel taps, value duplicated into a pair so LDS.128 yields ready f32x2 operands:
    // ks2[tap][cc][o_local][2], both halves equal
    __shared__ __align__(16) float ks2[9][CC][8][2];

    const int tid = threadIdx.x;
    const int wq     = tid & 31;
    const int h_pair = (tid >> 5) & 1;
    const int og     = tid >> 6;          // 0..1

    const int h0 = blockIdx.x * 4;
    const int o0 = blockIdx.y * 8;
    const int b  = blockIdx.z;

    // acc[oo][h][w]
    float acc[4][2][2];
#pragma unroll
    for (int oo = 0; oo < 4; oo++)
#pragma unroll
        for (int r = 0; r < 2; r++) {
            acc[oo][r][0] = NEGINF;
            acc[oo][r][1] = NEGINF;
        }

    const int scol = tid & 63;      // column within a staging row-job
    const int rsel = tid >> 6;      // 0..1: which of 2 concurrent row-jobs

    for (int q = 0; q < C_ / CC; q++) {
        const int c0 = q * CC;

        __syncthreads();   // protect xs/ks2 reuse from previous chunk

        // ---- stage x tile: CC channels x 6 rows, cols -1..64 ----
#pragma unroll
        for (int cc2 = 0; cc2 < CC / 2; cc2++) {
            const int cc = cc2 * 2 + rsel;
            const float* xp = x + ((size_t)(b * C_ + c0 + cc)) * (H_ * W_);
#pragma unroll
            for (int r = 0; r < 6; r++) {
                const int gh = h0 - 1 + r;
                const bool hok = ((unsigned)gh < (unsigned)H_);
                const float* src = xp + gh * W_;
                xs[cc][r][scol] = (hok && scol >= 1) ? src[scol - 1] : NEGINF;
                if (scol < 2) {
                    const int col = 64 + scol;           // gw = 63, 64
                    const int gw  = col - 1;
                    xs[cc][r][col] = (hok && gw < W_) ? src[gw] : NEGINF;
                }
            }
        }

        // ---- stage duplicated kernel taps: 9*CC*8*2 = 1152 floats, 9 per thread ----
        for (int f = tid; f < 9 * CC * 8 * 2; f += 128) {
            const int ol  = (f >> 1) & 7;
            const int cc  = (f >> 4) & (CC - 1);
            const int tap = f >> (4 + 3);   // f / (CC*8*2) with CC=8
            ks2[tap][cc][ol][f & 1] = kern[((o0 + ol) * C_ + (c0 + cc)) * 9 + tap];
        }

        __syncthreads();

        // ---- compute ----
#pragma unroll 1
        for (int cc = 0; cc < CC; cc++) {
            // load 4 staged rows (h_pair*2 + 0..3), 4 floats each, build packed col-pairs
            // xp2[r][kj] = (x[kj], x[kj+1]) for kj = 0..2
            unsigned long long xp2[4][3];
#pragma unroll
            for (int r = 0; r < 4; r++) {
                const float* rb = &xs[cc][h_pair * 2 + r][wq * 2];
                const float2 a0 = *(const float2*)(rb);
                const float2 a1 = *(const float2*)(rb + 2);
                xp2[r][0] = pack2(a0.x, a0.y);
                xp2[r][1] = pack2(a0.y, a1.x);
                xp2[r][2] = pack2(a1.x, a1.y);
            }
#pragma unroll
            for (int ki = 0; ki < 3; ki++) {
#pragma unroll
                for (int kj = 0; kj < 3; kj++) {
                    const int t = ki * 3 + kj;
                    // packed taps for this thread's 4 o's: two LDS.128
                    const ulonglong2 kA = *(const ulonglong2*)&ks2[t][cc][og * 4][0];     // o0, o1
                    const ulonglong2 kB = *(const ulonglong2*)&ks2[t][cc][og * 4 + 2][0]; // o2, o3
                    const unsigned long long kk[4] = { kA.x, kA.y, kB.x, kB.y };
#pragma unroll
                    for (int oo = 0; oo < 4; oo++) {
#pragma unroll
                        for (int r = 0; r < 2; r++) {
                            const unsigned long long s = addx2(xp2[r + ki][kj], kk[oo]);
                            float s0, s1;
                            unpack2(s, s0, s1);
                            acc[oo][r][0] = fmaxf(acc[oo][r][0], s0);
                            acc[oo][r][1] = fmaxf(acc[oo][r][1], s1);
                        }
                    }
                }
            }
        }
    }

    // ---- write out: out[b][o][h][w] ----
#pragma unroll
    for (int oo = 0; oo < 4; oo++) {
        const int o = o0 + og * 4 + oo;
#pragma unroll
        for (int r = 0; r < 2; r++) {
            const int h = h0 + h_pair * 2 + r;
            float* dst = out + (((size_t)(b * O_ + o)) * H_ + h) * W_ + wq * 2;
            *(float2*)dst = make_float2(acc[oo][r][0], acc[oo][r][1]);
        }
    }
}

extern "C" void kernel_launch(void* const* d_in, const int* in_sizes, int n_in,
                              void* d_out, int out_size)
{
    const float* x    = (const float*)d_in[0];   // [8,64,64,64]
    const float* kern = (const float*)d_in[1];   // [64,64,3,3]
    float* out        = (float*)d_out;           // [8,64,64,64]

    dim3 grid(H_ / 4, O_ / 8, B_);   // (16, 8, 8) = 1024 blocks
    dim3 block(128);
    maxplus_conv_kernel<<<grid, block>>>(x, kern, out);
}

// round 11
// speedup vs baseline: 1.0240x; 1.0240x over previous
#include <cuda_runtime.h>

#define NEGINF __int_as_float(0xff800000)

// Problem constants
#define B_ 8
#define C_ 64
#define H_ 64
#define W_ 64
#define O_ 64
#define CC 8    // channel chunk held in smem

// Block: 256 threads (R7 shape).
//   wq      = tid & 31      (0..31) -> output cols wq*2, wq*2+1
//   h_local = (tid >> 5)&1  (0..1)  -> output row within 2-row tile
//   og      = tid >> 6      (0..3)  -> o_local = og*4 .. og*4+3
// Grid: (32 h-tiles, 4 o-tiles, 8 batch) = 1024 blocks = 55 warps/SM.
//
// f32x2 packing over the O dimension:
//   taps contiguous in o  -> LDS.128 gives (k_o0,k_o1),(k_o2,k_o3) pairs FREE
//   x duplicated in smem  -> LDS.128 gives (x,x),(x',x') pairs FREE
//   per cc: 36 FADD2 (fma pipe) + 72 FMNMX (alu pipe) + 15 LDS, zero pack MOVs.

__device__ __forceinline__ unsigned long long addx2(unsigned long long a, unsigned long long b) {
    unsigned long long r;
    asm("add.rn.f32x2 %0, %1, %2;" : "=l"(r) : "l"(a), "l"(b));
    return r;
}
__device__ __forceinline__ void unpack2(unsigned long long v, float& lo, float& hi) {
    asm("mov.b64 {%0, %1}, %2;" : "=f"(lo), "=f"(hi) : "l"(v));
}

__global__ __launch_bounds__(256) void maxplus_conv_kernel(
    const float* __restrict__ x,
    const float* __restrict__ kern,
    float* __restrict__ out)
{
    // x tile, DUPLICATED values: rows h0-1..h0+2 (4 rows), cols -1..64 (66 cols),
    // value of col c stored at float indices 2c and 2c+1. Row = 132 floats = 528 B.
    __shared__ __align__(16) float xs2[CC][4][132];
    // taps: ks[tap][cc][o_local], contiguous in o for free pair loads
    __shared__ __align__(16) float ks[9][CC][16];

    const int tid = threadIdx.x;
    const int wq      = tid & 31;
    const int h_local = (tid >> 5) & 1;
    const int og      = tid >> 6;        // 0..3

    const int h0 = blockIdx.x * 2;
    const int o0 = blockIdx.y * 16;
    const int b  = blockIdx.z;

    // acc[o_local 0..3][w 0..1], scalar fp32
    float acc[4][2];
#pragma unroll
    for (int oo = 0; oo < 4; oo++) {
        acc[oo][0] = NEGINF;
        acc[oo][1] = NEGINF;
    }

    const int scol = tid & 63;      // column within a staging row-job
    const int rsel = tid >> 6;      // 0..3: which of 4 concurrent row-jobs

    for (int q = 0; q < C_ / CC; q++) {
        const int c0 = q * CC;

        __syncthreads();   // protect xs2/ks reuse from previous chunk

        // ---- stage x tile (duplicated): CC channels x 4 rows, cols -1..64 ----
        // 32 (cc,r) jobs, 4 in flight -> 8 iterations
#pragma unroll
        for (int j4 = 0; j4 < (CC * 4) / 4; j4++) {
            const int j  = j4 * 4 + rsel;
            const int cc = j >> 2;
            const int r  = j & 3;
            const int gh = h0 - 1 + r;
            const bool hok = ((unsigned)gh < (unsigned)H_);
            const float* src = x + ((size_t)((b * C_ + c0 + cc) * H_ + gh)) * W_;
            float2* drow = (float2*)&xs2[cc][r][0];
            {
                const float v = (hok && scol >= 1) ? src[scol - 1] : NEGINF;
                drow[scol] = make_float2(v, v);          // col = scol
            }
            if (scol < 2) {
                const int col = 64 + scol;               // gw = 63, 64
                const int gw  = col - 1;
                const float v = (hok && gw < W_) ? src[gw] : NEGINF;
                drow[col] = make_float2(v, v);
            }
        }

        // ---- stage kernel chunk: ks[tap][cc][ol] = kern[((o0+ol)*C + c0+cc)*9 + tap] ----
        for (int idx = tid; idx < 9 * CC * 16; idx += 256) {
            const int ol  = idx & 15;
            const int cc  = (idx >> 4) & (CC - 1);
            const int tap = idx >> 7;                    // idx / (CC*16), CC=8
            ks[tap][cc][ol] = kern[((o0 + ol) * C_ + (c0 + cc)) * 9 + tap];
        }

        __syncthreads();

        // ---- compute ----
#pragma unroll 1
        for (int cc = 0; cc < CC; cc++) {
#pragma unroll
            for (int ki = 0; ki < 3; ki++) {
                // duplicated x row segment: cols wq*2 .. wq*2+3 -> float idx 4wq .. 4wq+7
                // two LDS.128 -> four ready (x,x) register pairs
                const ulonglong2 uA = *(const ulonglong2*)&xs2[cc][h_local + ki][wq * 4];
                const ulonglong2 uB = *(const ulonglong2*)&xs2[cc][h_local + ki][wq * 4 + 4];
                const unsigned long long dupx[4] = { uA.x, uA.y, uB.x, uB.y };
#pragma unroll
                for (int kj = 0; kj < 3; kj++) {
                    const int t = ki * 3 + kj;
                    // tap pairs for this thread's 4 o's: one LDS.128 -> (k0,k1),(k2,k3)
                    const ulonglong2 kp = *(const ulonglong2*)&ks[t][cc][og * 4];
#pragma unroll
                    for (int w = 0; w < 2; w++) {
                        const unsigned long long xv = dupx[w + kj];   // (x,x) at col w+kj
                        {
                            const unsigned long long s = addx2(xv, kp.x);  // (x+k0, x+k1)
                            float s0, s1; unpack2(s, s0, s1);
                            acc[0][w] = fmaxf(acc[0][w], s0);
                            acc[1][w] = fmaxf(acc[1][w], s1);
                        }
                        {
                            const unsigned long long s = addx2(xv, kp.y);  // (x+k2, x+k3)
                            float s0, s1; unpack2(s, s0, s1);
                            acc[2][w] = fmaxf(acc[2][w], s0);
                            acc[3][w] = fmaxf(acc[3][w], s1);
                        }
                    }
                }
            }
        }
    }

    // ---- write out: out[b][o][h][w], o = o0 + og*4 + oo, h = h0+h_local, w = wq*2 + i ----
    const int h = h0 + h_local;
#pragma unroll
    for (int oo = 0; oo < 4; oo++) {
        const int o = o0 + og * 4 + oo;
        float* dst = out + (((size_t)(b * O_ + o)) * H_ + h) * W_ + wq * 2;
        *(float2*)dst = make_float2(acc[oo][0], acc[oo][1]);
    }
}

extern "C" void kernel_launch(void* const* d_in, const int* in_sizes, int n_in,
                              void* d_out, int out_size)
{
    const float* x    = (const float*)d_in[0];   // [8,64,64,64]
    const float* kern = (const float*)d_in[1];   // [64,64,3,3]
    float* out        = (float*)d_out;           // [8,64,64,64]

    dim3 grid(H_ / 2, O_ / 16, B_);   // (32, 4, 8) = 1024 blocks
    dim3 block(256);
    maxplus_conv_kernel<<<grid, block>>>(x, kern, out);
}